// round 16
// baseline (speedup 1.0000x reference)
#include <cuda_runtime.h>
#include <cuda_fp16.h>
#include <cstdint>

#define BATCH 4
#define SEQ   1024
#define NXD   1024
#define NHEAD 16
#define HDIM  64
#define GK    1024

// Scratch (allocation-free rule: __device__ globals) — fp16 internals
__device__ __half g_q[(size_t)BATCH * NHEAD * SEQ * HDIM];
__device__ __half g_k[(size_t)BATCH * NHEAD * SEQ * HDIM];
__device__ __half g_v[(size_t)BATCH * NHEAD * SEQ * HDIM];
__device__ __half g_a[(size_t)BATCH * SEQ * NXD];
__device__ __half g_x[(size_t)BATCH * SEQ * NXD];
__device__ __half g_wT_attn[(size_t)3 * NXD * NXD];          // [3072,1024]
__device__ __half g_wT_proj[(size_t)NXD * NXD];              // [1024,1024]

// work-queue state (zero-init at load; reset by last worker each run)
__device__ int g_cursor;
__device__ int g_finished;
__device__ int g_x_done[32];
__device__ int g_wa_done[24];
__device__ int g_wp_done[8];
__device__ int g_qkv_done[32];    // per (b*8 + sblock128), target 24
__device__ int g_attn_done[32];   // per (b*8 + qtile128), target 16

#define N_PREP  64
#define N_QKV   768
#define N_ATTN  512
#define N_PROJ  256
#define N_ITEMS (N_PREP + N_QKV + N_ATTN + N_PROJ)   // 1600
#define N_WORKERS 296

__device__ __forceinline__ uint32_t smem_u32(const void* p) {
    uint32_t a;
    asm("{ .reg .u64 t; cvta.to.shared.u64 t, %1; cvt.u32.u64 %0, t; }"
        : "=r"(a) : "l"(p));
    return a;
}
__device__ __forceinline__ uint32_t packh2(float a, float b) {
    __half2 h = __floats2half2_rn(a, b);
    return *(uint32_t*)&h;
}
__device__ __forceinline__ void cp16(uint32_t dst, const void* src) {
    asm volatile("cp.async.cg.shared.global [%0], [%1], 16;"
                 :: "r"(dst), "l"(src) : "memory");
}
__device__ __forceinline__ void cp_commit() {
    asm volatile("cp.async.commit_group;" ::: "memory");
}
__device__ __forceinline__ void mma_f16(float* d,
    uint32_t a0, uint32_t a1, uint32_t a2, uint32_t a3,
    uint32_t b0, uint32_t b1)
{
    asm volatile(
        "mma.sync.aligned.m16n8k16.row.col.f32.f16.f16.f32 "
        "{%0,%1,%2,%3}, {%4,%5,%6,%7}, {%8,%9}, {%0,%1,%2,%3};"
        : "+f"(d[0]), "+f"(d[1]), "+f"(d[2]), "+f"(d[3])
        : "r"(a0), "r"(a1), "r"(a2), "r"(a3), "r"(b0), "r"(b1));
}
__device__ __forceinline__ void ldsm4(uint32_t* r, uint32_t addr) {
    asm volatile("ldmatrix.sync.aligned.m8n8.x4.shared.b16 {%0,%1,%2,%3}, [%4];"
                 : "=r"(r[0]), "=r"(r[1]), "=r"(r[2]), "=r"(r[3]) : "r"(addr));
}
__device__ __forceinline__ void ldsm4t(uint32_t* r, uint32_t addr) {
    asm volatile("ldmatrix.sync.aligned.m8n8.x4.trans.shared.b16 {%0,%1,%2,%3}, [%4];"
                 : "=r"(r[0]), "=r"(r[1]), "=r"(r[2]), "=r"(r[3]) : "r"(addr));
}
__device__ __forceinline__ void spin_until(volatile int* p, int target) {
    while (*p < target) __nanosleep(200);
}

#define QSCALE 0.18033688011112042f   // (1/8) * log2(e)

#define TLD2 36
#define STG32 (256 * TLD2)
#define FUSED_SMEM (3 * STG32 * 4)    // 110,592 B

// ---------------------------------------------------------------------------
// Prep roles
// ---------------------------------------------------------------------------
__device__ void run_xcopy(int m, const float* __restrict__ x)
{
    // m-block: float4 chunks [m*32768, (m+1)*32768)
    const int base = m * 32768;
    for (int k = threadIdx.x; k < 32768; k += 256) {
        float4 v = ((const float4*)x)[base + k];
        uint2 o;
        o.x = packh2(v.x, v.y);
        o.y = packh2(v.z, v.w);
        ((uint2*)g_x)[base + k] = o;
    }
}

// transpose 128 source columns [n0,n0+128) of src[1024][C] into dst rows.
__device__ void run_wtrans(const float* __restrict__ src, __half* __restrict__ dst,
                           int C, int n0, float (*tile)[33])
{
    const int tx = threadIdx.x & 31, ty = threadIdx.x >> 5;
    for (int tt = 0; tt < 128; tt++) {
        const int r0 = (tt >> 2) * 32;
        const int c0 = n0 + (tt & 3) * 32;
#pragma unroll
        for (int i = 0; i < 32; i += 8)
            tile[ty + i][tx] = src[(size_t)(r0 + ty + i) * C + c0 + tx];
        __syncthreads();
#pragma unroll
        for (int i = 0; i < 32; i += 8)
            dst[(size_t)(c0 + ty + i) * NXD + r0 + tx] = __float2half(tile[tx][ty + i]);
        __syncthreads();
    }
}

// ---------------------------------------------------------------------------
// GEMM role: block tile 128x128, BK=64, ldmatrix, 3-stage cp.async
// ---------------------------------------------------------------------------
__device__ void run_gemm(
    const __half* __restrict__ A, const __half* __restrict__ BT,
    const float* __restrict__ bias, float* __restrict__ Cout,
    float* __restrict__ present, int mode, int m0, int n0, uint32_t* sm32)
{
    const int t = threadIdx.x;
    const int lane = t & 31, w = t >> 5;
    const int wm = w >> 1, wn = w & 1;
    const int qr = lane >> 2, qc = lane & 3;

    uint32_t sa_[3], sb_[3];
#pragma unroll
    for (int s = 0; s < 3; s++) {
        sa_[s] = smem_u32(sm32 + s * STG32);
        sb_[s] = sa_[s] + 128 * TLD2 * 4;
    }

    const uint32_t a_loff = ((wm * 32 + (lane & 15)) * TLD2 + ((lane >> 4) << 2)) * 4;
    const uint32_t b_loff = ((wn * 64 + ((lane >> 4) << 3) + (lane & 7)) * TLD2
                             + (((lane >> 3) & 1) << 2)) * 4;

    float acc[2][8][4];
#pragma unroll
    for (int mt = 0; mt < 2; mt++)
#pragma unroll
        for (int nt = 0; nt < 8; nt++)
#pragma unroll
            for (int r = 0; r < 4; r++) acc[mt][nt][r] = 0.f;

#pragma unroll
    for (int s = 0; s < 2; s++) {
        const int k0 = s * 64;
#pragma unroll
        for (int i = 0; i < 4; i++) {
            int idx = t + i * 256;
            int row = idx >> 3, ch = idx & 7;
            cp16(sa_[s] + ((uint32_t)row * TLD2 + ch * 4) * 4,
                 A + (size_t)(m0 + row) * GK + k0 + ch * 8);
            cp16(sb_[s] + ((uint32_t)row * TLD2 + ch * 4) * 4,
                 BT + (size_t)(n0 + row) * GK + k0 + ch * 8);
        }
        cp_commit();
    }

    for (int kb = 0; kb < 16; kb++) {
        if (kb < 14)
            asm volatile("cp.async.wait_group 1;" ::: "memory");
        else
            asm volatile("cp.async.wait_group 0;" ::: "memory");
        __syncthreads();

        if (kb + 2 < 16) {
            const int s = (kb + 2) % 3;
            const int k0 = (kb + 2) * 64;
#pragma unroll
            for (int i = 0; i < 4; i++) {
                int idx = t + i * 256;
                int row = idx >> 3, ch = idx & 7;
                cp16(sa_[s] + ((uint32_t)row * TLD2 + ch * 4) * 4,
                     A + (size_t)(m0 + row) * GK + k0 + ch * 8);
                cp16(sb_[s] + ((uint32_t)row * TLD2 + ch * 4) * 4,
                     BT + (size_t)(n0 + row) * GK + k0 + ch * 8);
            }
            cp_commit();
        }

        const uint32_t a_addr = sa_[kb % 3] + a_loff;
        const uint32_t b_addr = sb_[kb % 3] + b_loff;
#pragma unroll
        for (int ks = 0; ks < 4; ks++) {
            uint32_t af[2][4], bf[4][4];
            ldsm4(af[0], a_addr + ks * 32);
            ldsm4(af[1], a_addr + 16 * TLD2 * 4 + ks * 32);
#pragma unroll
            for (int p = 0; p < 4; p++)
                ldsm4(bf[p], b_addr + p * 16 * TLD2 * 4 + ks * 32);
#pragma unroll
            for (int mt = 0; mt < 2; mt++)
#pragma unroll
                for (int nt = 0; nt < 8; nt++)
                    mma_f16(acc[mt][nt], af[mt][0], af[mt][1], af[mt][2], af[mt][3],
                            bf[nt >> 1][(nt & 1) * 2], bf[nt >> 1][(nt & 1) * 2 + 1]);
        }
    }

#pragma unroll
    for (int mt = 0; mt < 2; mt++) {
#pragma unroll
        for (int nt = 0; nt < 8; nt++) {
            int row = m0 + wm * 32 + mt * 16 + qr;
            int col = n0 + wn * 64 + nt * 8 + qc * 2;
            float bv0 = bias[col], bv1 = bias[col + 1];
            float v00 = acc[mt][nt][0] + bv0, v01 = acc[mt][nt][1] + bv1;
            float v10 = acc[mt][nt][2] + bv0, v11 = acc[mt][nt][3] + bv1;
            if (mode == 1) {
                *(float2*)(Cout + (size_t)row * NXD + col) = make_float2(v00, v01);
                *(float2*)(Cout + (size_t)(row + 8) * NXD + col) = make_float2(v10, v11);
            } else {
                int sec = col >> 10;
                int hn = col & 1023;
                int h = hn >> 6, d = hn & 63;
                int b0_ = row >> 10, s0_ = row & 1023;
                size_t i0 = (((size_t)b0_ * NHEAD + h) * SEQ + s0_) * HDIM + d;
                int b1_ = (row + 8) >> 10, s1_ = (row + 8) & 1023;
                size_t i1 = (((size_t)b1_ * NHEAD + h) * SEQ + s1_) * HDIM + d;
                if (sec == 0) {
                    *(uint32_t*)(g_q + i0) = packh2(v00 * QSCALE, v01 * QSCALE);
                    *(uint32_t*)(g_q + i1) = packh2(v10 * QSCALE, v11 * QSCALE);
                } else if (sec == 1) {
                    *(float2*)(present + i0) = make_float2(v00, v01);
                    *(float2*)(present + i1) = make_float2(v10, v11);
                    *(uint32_t*)(g_k + i0) = packh2(v00, v01);
                    *(uint32_t*)(g_k + i1) = packh2(v10, v11);
                } else {
                    float* pv = present + (size_t)BATCH * NHEAD * SEQ * HDIM;
                    *(float2*)(pv + i0) = make_float2(v00, v01);
                    *(float2*)(pv + i1) = make_float2(v10, v11);
                    *(uint32_t*)(g_v + i0) = packh2(v00, v01);
                    *(uint32_t*)(g_v + i1) = packh2(v10, v11);
                }
            }
        }
    }
}

// ---------------------------------------------------------------------------
// Attention role (R14-verified)
// ---------------------------------------------------------------------------
__device__ void run_attn(int xr, int h, int b, uint32_t* sm32)
{
    uint32_t* Qs = sm32;
    uint32_t* Ksb = Qs + 128 * TLD2;
    uint32_t* Vsb = Ksb + 2 * 64 * TLD2;

    const int t = threadIdx.x;
    const int lane = t & 31, w = t >> 5;
    const int qr = lane >> 2, qc = lane & 3;
    const int q0 = xr * 128;

    const __half* qptr = g_q + ((size_t)b * NHEAD + h) * SEQ * HDIM;
    const __half* kptr = g_k + ((size_t)b * NHEAD + h) * SEQ * HDIM;
    const __half* vptr = g_v + ((size_t)b * NHEAD + h) * SEQ * HDIM;

    const uint32_t qs_a = smem_u32(Qs);
    const uint32_t ks_a[2] = { smem_u32(Ksb), smem_u32(Ksb + 64 * TLD2) };
    const uint32_t vs_a[2] = { smem_u32(Vsb), smem_u32(Vsb + 64 * TLD2) };

    const int wrow = w * 16;
    const uint32_t qa_loff = ((wrow + (lane & 15)) * TLD2 + ((lane >> 4) << 2)) * 4;
    const uint32_t kb_loff = ((((lane >> 4) << 3) + (lane & 7)) * TLD2
                              + (((lane >> 3) & 1) << 2)) * 4;
    const uint32_t vt_loff = (((((lane >> 3) & 1) << 3) + (lane & 7)) * TLD2
                              + ((lane >> 4) << 2)) * 4;

#pragma unroll
    for (int i = 0; i < 4; i++) {
        int c = t + i * 256;
        int row = c >> 3, ch = c & 7;
        cp16(qs_a + ((uint32_t)row * TLD2 + ch * 4) * 4,
             qptr + (size_t)(q0 + row) * HDIM + ch * 8);
    }
#pragma unroll
    for (int i = 0; i < 2; i++) {
        int c = t + i * 256;
        int row = c >> 3, ch = c & 7;
        uint32_t off = ((uint32_t)row * TLD2 + ch * 4) * 4;
        cp16(ks_a[0] + off, kptr + (size_t)row * HDIM + ch * 8);
        cp16(vs_a[0] + off, vptr + (size_t)row * HDIM + ch * 8);
    }
    cp_commit();

    float oacc[8][4];
#pragma unroll
    for (int nt = 0; nt < 8; nt++)
#pragma unroll
        for (int r = 0; r < 4; r++) oacc[nt][r] = 0.f;
    float m0 = -1e30f, m1 = -1e30f, l0 = 0.f, l1 = 0.f;

    const int qg0 = q0 + wrow + qr;
    const int qg1 = qg0 + 8;
    const int qmax = q0 + wrow + 15;
    const int nj = xr * 2 + 2;

    asm volatile("cp.async.wait_group 0;" ::: "memory");
    __syncthreads();
    uint32_t qf[4][4];
#pragma unroll
    for (int ks = 0; ks < 4; ks++)
        ldsm4(qf[ks], qs_a + qa_loff + ks * 32);

    for (int jt = 0; jt < nj; jt++) {
        const int j0 = jt * 64;
        if (jt > 0) {
            asm volatile("cp.async.wait_group 0;" ::: "memory");
            __syncthreads();
        }
        if (jt + 1 < nj) {
            const int buf = (jt + 1) & 1;
            const int jr = (jt + 1) * 64;
#pragma unroll
            for (int i = 0; i < 2; i++) {
                int c = t + i * 256;
                int row = c >> 3, ch = c & 7;
                uint32_t off = ((uint32_t)row * TLD2 + ch * 4) * 4;
                cp16(ks_a[buf] + off, kptr + (size_t)(jr + row) * HDIM + ch * 8);
                cp16(vs_a[buf] + off, vptr + (size_t)(jr + row) * HDIM + ch * 8);
            }
            cp_commit();
        }
        if (j0 > qmax) continue;

        const uint32_t k_addr = ks_a[jt & 1] + kb_loff;
        const uint32_t v_addr = vs_a[jt & 1] + vt_loff;

        float sacc[8][4];
#pragma unroll
        for (int nt = 0; nt < 8; nt++)
#pragma unroll
            for (int r = 0; r < 4; r++) sacc[nt][r] = 0.f;

#pragma unroll
        for (int ks = 0; ks < 4; ks++) {
            uint32_t kf[4][4];
#pragma unroll
            for (int p = 0; p < 4; p++)
                ldsm4(kf[p], k_addr + p * 16 * TLD2 * 4 + ks * 32);
#pragma unroll
            for (int nt = 0; nt < 8; nt++)
                mma_f16(sacc[nt], qf[ks][0], qf[ks][1], qf[ks][2], qf[ks][3],
                        kf[nt >> 1][(nt & 1) * 2], kf[nt >> 1][(nt & 1) * 2 + 1]);
        }

        float rx0 = -1e30f, rx1 = -1e30f;
        if (j0 + 63 > q0 + wrow) {
#pragma unroll
            for (int nt = 0; nt < 8; nt++) {
                int kg = j0 + nt * 8 + qc * 2;
                if (kg > qg0)     sacc[nt][0] = -1e30f;
                if (kg + 1 > qg0) sacc[nt][1] = -1e30f;
                if (kg > qg1)     sacc[nt][2] = -1e30f;
                if (kg + 1 > qg1) sacc[nt][3] = -1e30f;
            }
        }
#pragma unroll
        for (int nt = 0; nt < 8; nt++) {
            rx0 = fmaxf(rx0, fmaxf(sacc[nt][0], sacc[nt][1]));
            rx1 = fmaxf(rx1, fmaxf(sacc[nt][2], sacc[nt][3]));
        }
        rx0 = fmaxf(rx0, __shfl_xor_sync(0xffffffffu, rx0, 1));
        rx0 = fmaxf(rx0, __shfl_xor_sync(0xffffffffu, rx0, 2));
        rx1 = fmaxf(rx1, __shfl_xor_sync(0xffffffffu, rx1, 1));
        rx1 = fmaxf(rx1, __shfl_xor_sync(0xffffffffu, rx1, 2));

        float nm0 = fmaxf(m0, rx0), nm1 = fmaxf(m1, rx1);
        float cr0 = exp2f(m0 - nm0), cr1 = exp2f(m1 - nm1);

        float rs0 = 0.f, rs1 = 0.f;
        uint32_t plo[8], phi[8];
#pragma unroll
        for (int nt = 0; nt < 8; nt++) {
            float p00 = exp2f(sacc[nt][0] - nm0);
            float p01 = exp2f(sacc[nt][1] - nm0);
            float p10 = exp2f(sacc[nt][2] - nm1);
            float p11 = exp2f(sacc[nt][3] - nm1);
            rs0 += p00 + p01;
            rs1 += p10 + p11;
            plo[nt] = packh2(p00, p01);
            phi[nt] = packh2(p10, p11);
        }
        rs0 += __shfl_xor_sync(0xffffffffu, rs0, 1);
        rs0 += __shfl_xor_sync(0xffffffffu, rs0, 2);
        rs1 += __shfl_xor_sync(0xffffffffu, rs1, 1);
        rs1 += __shfl_xor_sync(0xffffffffu, rs1, 2);

        l0 = l0 * cr0 + rs0;  m0 = nm0;
        l1 = l1 * cr1 + rs1;  m1 = nm1;
#pragma unroll
        for (int nt = 0; nt < 8; nt++) {
            oacc[nt][0] *= cr0;  oacc[nt][1] *= cr0;
            oacc[nt][2] *= cr1;  oacc[nt][3] *= cr1;
        }

#pragma unroll
        for (int j = 0; j < 4; j++) {
            uint32_t vf[4][4];
#pragma unroll
            for (int p = 0; p < 4; p++)
                ldsm4t(vf[p], v_addr + j * 16 * TLD2 * 4 + p * 32);
            uint32_t a0 = plo[2 * j], a1 = phi[2 * j];
            uint32_t a2 = plo[2 * j + 1], a3 = phi[2 * j + 1];
#pragma unroll
            for (int nt = 0; nt < 8; nt++)
                mma_f16(oacc[nt], a0, a1, a2, a3,
                        vf[nt >> 1][(nt & 1) * 2], vf[nt >> 1][(nt & 1) * 2 + 1]);
        }
    }

    __syncthreads();
    float inv0 = 1.f / l0, inv1 = 1.f / l1;
#pragma unroll
    for (int nt = 0; nt < 8; nt++) {
        Qs[(wrow + qr) * TLD2 + nt * 4 + qc] =
            packh2(oacc[nt][0] * inv0, oacc[nt][1] * inv0);
        Qs[(wrow + qr + 8) * TLD2 + nt * 4 + qc] =
            packh2(oacc[nt][2] * inv1, oacc[nt][3] * inv1);
    }
    __syncthreads();
    for (int idx = t; idx < 128 * 32; idx += 256) {
        int row = idx >> 5, c2 = idx & 31;
        *(uint32_t*)(g_a + ((size_t)b * SEQ + q0 + row) * NXD + h * HDIM + c2 * 2) =
            Qs[row * TLD2 + c2];
    }
}

// ---------------------------------------------------------------------------
// Single persistent kernel: prep + qkv + attn + proj via one work queue.
// ---------------------------------------------------------------------------
__global__ void __launch_bounds__(256, 2) fused_kernel(
    const float* __restrict__ x, const float* __restrict__ w_attn,
    const float* __restrict__ w_proj,
    const float* __restrict__ b_attn, const float* __restrict__ b_proj,
    float* __restrict__ out, float* __restrict__ present)
{
    extern __shared__ uint32_t sm32[];
    __shared__ int s_item;

    for (;;) {
        if (threadIdx.x == 0) s_item = atomicAdd(&g_cursor, 1);
        __syncthreads();
        const int i = s_item;
        if (i >= N_ITEMS) break;

        if (i < 32) {                       // x -> fp16 copy, m-block
            run_xcopy(i, x);
            __syncthreads();
            if (threadIdx.x == 0) { __threadfence(); atomicExch(&g_x_done[i], 1); }
        } else if (i < 56) {                // w_attn transpose, n-block
            const int n = i - 32;
            run_wtrans(w_attn, g_wT_attn, 3 * NXD, n * 128, (float(*)[33])sm32);
            __syncthreads();
            if (threadIdx.x == 0) { __threadfence(); atomicExch(&g_wa_done[n], 1); }
        } else if (i < 64) {                // w_proj transpose, n-block
            const int n = i - 56;
            run_wtrans(w_proj, g_wT_proj, NXD, n * 128, (float(*)[33])sm32);
            __syncthreads();
            if (threadIdx.x == 0) { __threadfence(); atomicExch(&g_wp_done[n], 1); }
        } else if (i < N_PREP + N_QKV) {    // qkv tile
            const int q = i - N_PREP;
            const int m = q / 24, n = q % 24;
            if (threadIdx.x == 0) {
                spin_until(&g_x_done[m], 1);
                spin_until(&g_wa_done[n], 1);
            }
            __syncthreads();
            __threadfence();
            run_gemm(g_x, g_wT_attn, b_attn, nullptr, present, 0,
                     m * 128, n * 128, sm32);
            __syncthreads();
            if (threadIdx.x == 0) { __threadfence(); atomicAdd(&g_qkv_done[m], 1); }
        } else if (i < N_PREP + N_QKV + N_ATTN) {   // attn tile (long-first)
            const int j = i - N_PREP - N_QKV;
            const int xr = 7 - (j >> 6);
            const int h = (j & 63) >> 2;
            const int b = j & 3;
            if (threadIdx.x == 0)
                for (int s = 0; s <= xr; s++)
                    spin_until(&g_qkv_done[b * 8 + s], 24);
            __syncthreads();
            __threadfence();
            run_attn(xr, h, b, sm32);
            __syncthreads();
            if (threadIdx.x == 0) { __threadfence(); atomicAdd(&g_attn_done[b * 8 + xr], 1); }
        } else {                            // proj tile
            const int p = i - N_PREP - N_QKV - N_ATTN;
            const int m = p >> 3, n = p & 7;
            if (threadIdx.x == 0) {
                spin_until(&g_wp_done[n], 1);
                spin_until(&g_attn_done[m], 16);
            }
            __syncthreads();
            __threadfence();
            run_gemm(g_a, g_wT_proj, b_proj, out, nullptr, 1,
                     m * 128, n * 128, sm32);
        }
        __syncthreads();
    }

    // last worker resets queue state for the next graph replay
    if (threadIdx.x == 0) {
        int f = atomicAdd(&g_finished, 1);
        if (f == N_WORKERS - 1) {
            g_cursor = 0;
            g_finished = 0;
#pragma unroll
            for (int k = 0; k < 32; k++) { g_x_done[k] = 0; g_qkv_done[k] = 0; g_attn_done[k] = 0; }
#pragma unroll
            for (int k = 0; k < 24; k++) g_wa_done[k] = 0;
#pragma unroll
            for (int k = 0; k < 8; k++) g_wp_done[k] = 0;
            __threadfence();
        }
    }
}

// ---------------------------------------------------------------------------
extern "C" void kernel_launch(void* const* d_in, const int* in_sizes, int n_in,
                              void* d_out, int out_size)
{
    const float* x      = (const float*)d_in[0];
    const float* w_attn = (const float*)d_in[1];
    const float* b_attn = (const float*)d_in[2];
    const float* w_proj = (const float*)d_in[3];
    const float* b_proj = (const float*)d_in[4];

    float* out = (float*)d_out;
    float* present = out + (size_t)BATCH * SEQ * NXD;  // (2,B,NH,S,HD)

    cudaFuncSetAttribute(fused_kernel,
                         cudaFuncAttributeMaxDynamicSharedMemorySize, FUSED_SMEM);

    fused_kernel<<<N_WORKERS, 256, FUSED_SMEM>>>(
        x, w_attn, w_proj, b_attn, b_proj, out, present);
}

// round 17
// speedup vs baseline: 1.2445x; 1.2445x over previous
#include <cuda_runtime.h>
#include <cuda_fp16.h>
#include <cstdint>

#define BATCH 4
#define SEQ   1024
#define NXD   1024
#define NHEAD 16
#define HDIM  64
#define GK    1024

// Scratch (allocation-free rule: __device__ globals) — fp16 internals
__device__ __half g_q[(size_t)BATCH * NHEAD * SEQ * HDIM];   // pre-scaled by 0.125*log2(e)
__device__ __half g_k[(size_t)BATCH * NHEAD * SEQ * HDIM];
__device__ __half g_v[(size_t)BATCH * NHEAD * SEQ * HDIM];
__device__ __half g_a[(size_t)BATCH * SEQ * NXD];
__device__ __half g_x[(size_t)BATCH * SEQ * NXD];
__device__ __half g_wT_attn[(size_t)3 * NXD * NXD];          // [3072,1024]
__device__ __half g_wT_proj[(size_t)NXD * NXD];              // [1024,1024]

// work-queue state (re-zeroed by prep each launch)
__device__ int g_cursor;
__device__ int g_qkv_done[32];    // per (b*8 + sblock128), target 24
__device__ int g_attn_done[32];   // per (b*8 + qtile128), target 16

#define N_QKV  768
#define N_ATTN 512
#define N_ITEMS 1536

__device__ __forceinline__ uint32_t smem_u32(const void* p) {
    uint32_t a;
    asm("{ .reg .u64 t; cvta.to.shared.u64 t, %1; cvt.u32.u64 %0, t; }"
        : "=r"(a) : "l"(p));
    return a;
}
__device__ __forceinline__ uint32_t packh2(float a, float b) {
    __half2 h = __floats2half2_rn(a, b);
    return *(uint32_t*)&h;
}
__device__ __forceinline__ void cp16(uint32_t dst, const void* src) {
    asm volatile("cp.async.cg.shared.global [%0], [%1], 16;"
                 :: "r"(dst), "l"(src) : "memory");
}
__device__ __forceinline__ void cp_commit() {
    asm volatile("cp.async.commit_group;" ::: "memory");
}
__device__ __forceinline__ void mma_f16(float* d,
    uint32_t a0, uint32_t a1, uint32_t a2, uint32_t a3,
    uint32_t b0, uint32_t b1)
{
    asm volatile(
        "mma.sync.aligned.m16n8k16.row.col.f32.f16.f16.f32 "
        "{%0,%1,%2,%3}, {%4,%5,%6,%7}, {%8,%9}, {%0,%1,%2,%3};"
        : "+f"(d[0]), "+f"(d[1]), "+f"(d[2]), "+f"(d[3])
        : "r"(a0), "r"(a1), "r"(a2), "r"(a3), "r"(b0), "r"(b1));
}
__device__ __forceinline__ void ldsm4(uint32_t* r, uint32_t addr) {
    asm volatile("ldmatrix.sync.aligned.m8n8.x4.shared.b16 {%0,%1,%2,%3}, [%4];"
                 : "=r"(r[0]), "=r"(r[1]), "=r"(r[2]), "=r"(r[3]) : "r"(addr));
}
__device__ __forceinline__ void ldsm4t(uint32_t* r, uint32_t addr) {
    asm volatile("ldmatrix.sync.aligned.m8n8.x4.trans.shared.b16 {%0,%1,%2,%3}, [%4];"
                 : "=r"(r[0]), "=r"(r[1]), "=r"(r[2]), "=r"(r[3]) : "r"(addr));
}
__device__ __forceinline__ void spin_until(volatile int* p, int target) {
    while (*p < target) __nanosleep(200);
}

#define QSCALE 0.18033688011112042f   // (1/8) * log2(e)

#define TLD2 36
#define STG32 (256 * TLD2)
#define FUSED_SMEM (3 * STG32 * 4)    // 110,592 B

// ---------------------------------------------------------------------------
// prep: x->fp16, both weight transposes, queue/counter reset (one launch)
// ---------------------------------------------------------------------------
__global__ void __launch_bounds__(256) prep_kernel(
    const float* __restrict__ x,
    const float* __restrict__ w_attn,
    const float* __restrict__ w_proj)
{
    const int bid = blockIdx.x;
    if (bid == 0 && threadIdx.x < 65) {
        if (threadIdx.x == 64) g_cursor = 0;
        else if (threadIdx.x < 32) g_qkv_done[threadIdx.x] = 0;
        else g_attn_done[threadIdx.x - 32] = 0;
    }
    if (bid < 4096) {
        int i = bid * 256 + threadIdx.x;
        float4 v = ((const float4*)x)[i];
        uint2 o;
        o.x = packh2(v.x, v.y);
        o.y = packh2(v.z, v.w);
        ((uint2*)g_x)[i] = o;
        return;
    }
    __shared__ float tile[32][33];
    const float* src;  __half* dst;  int R, C, c0, r0;
    if (bid < 7168) {
        int b2 = bid - 4096;
        src = w_attn;  dst = g_wT_attn;  R = NXD;  C = 3 * NXD;
        c0 = (b2 % 96) * 32;  r0 = (b2 / 96) * 32;
    } else {
        int b2 = bid - 7168;
        src = w_proj;  dst = g_wT_proj;  R = NXD;  C = NXD;
        c0 = (b2 % 32) * 32;  r0 = (b2 / 32) * 32;
    }
    int tx = threadIdx.x & 31, ty = threadIdx.x >> 5;
#pragma unroll
    for (int i = 0; i < 32; i += 8)
        tile[ty + i][tx] = src[(size_t)(r0 + ty + i) * C + c0 + tx];
    __syncthreads();
#pragma unroll
    for (int i = 0; i < 32; i += 8)
        dst[(size_t)(c0 + ty + i) * R + r0 + tx] = __float2half(tile[tx][ty + i]);
}

// ---------------------------------------------------------------------------
// GEMM role: block tile 128x128, BK=64, ldmatrix, 3-stage cp.async
// ---------------------------------------------------------------------------
__device__ void run_gemm(
    const __half* __restrict__ A, const __half* __restrict__ BT,
    const float* __restrict__ bias, float* __restrict__ Cout,
    float* __restrict__ present, int mode, int m0, int n0, uint32_t* sm32)
{
    const int t = threadIdx.x;
    const int lane = t & 31, w = t >> 5;
    const int wm = w >> 1, wn = w & 1;
    const int qr = lane >> 2, qc = lane & 3;

    uint32_t sa_[3], sb_[3];
#pragma unroll
    for (int s = 0; s < 3; s++) {
        sa_[s] = smem_u32(sm32 + s * STG32);
        sb_[s] = sa_[s] + 128 * TLD2 * 4;
    }

    const uint32_t a_loff = ((wm * 32 + (lane & 15)) * TLD2 + ((lane >> 4) << 2)) * 4;
    const uint32_t b_loff = ((wn * 64 + ((lane >> 4) << 3) + (lane & 7)) * TLD2
                             + (((lane >> 3) & 1) << 2)) * 4;

    float acc[2][8][4];
#pragma unroll
    for (int mt = 0; mt < 2; mt++)
#pragma unroll
        for (int nt = 0; nt < 8; nt++)
#pragma unroll
            for (int r = 0; r < 4; r++) acc[mt][nt][r] = 0.f;

#pragma unroll
    for (int s = 0; s < 2; s++) {
        const int k0 = s * 64;
#pragma unroll
        for (int i = 0; i < 4; i++) {
            int idx = t + i * 256;
            int row = idx >> 3, ch = idx & 7;
            cp16(sa_[s] + ((uint32_t)row * TLD2 + ch * 4) * 4,
                 A + (size_t)(m0 + row) * GK + k0 + ch * 8);
            cp16(sb_[s] + ((uint32_t)row * TLD2 + ch * 4) * 4,
                 BT + (size_t)(n0 + row) * GK + k0 + ch * 8);
        }
        cp_commit();
    }

    for (int kb = 0; kb < 16; kb++) {
        if (kb < 14)
            asm volatile("cp.async.wait_group 1;" ::: "memory");
        else
            asm volatile("cp.async.wait_group 0;" ::: "memory");
        __syncthreads();

        if (kb + 2 < 16) {
            const int s = (kb + 2) % 3;
            const int k0 = (kb + 2) * 64;
#pragma unroll
            for (int i = 0; i < 4; i++) {
                int idx = t + i * 256;
                int row = idx >> 3, ch = idx & 7;
                cp16(sa_[s] + ((uint32_t)row * TLD2 + ch * 4) * 4,
                     A + (size_t)(m0 + row) * GK + k0 + ch * 8);
                cp16(sb_[s] + ((uint32_t)row * TLD2 + ch * 4) * 4,
                     BT + (size_t)(n0 + row) * GK + k0 + ch * 8);
            }
            cp_commit();
        }

        const uint32_t a_addr = sa_[kb % 3] + a_loff;
        const uint32_t b_addr = sb_[kb % 3] + b_loff;
#pragma unroll
        for (int ks = 0; ks < 4; ks++) {
            uint32_t af[2][4], bf[4][4];
            ldsm4(af[0], a_addr + ks * 32);
            ldsm4(af[1], a_addr + 16 * TLD2 * 4 + ks * 32);
#pragma unroll
            for (int p = 0; p < 4; p++)
                ldsm4(bf[p], b_addr + p * 16 * TLD2 * 4 + ks * 32);
#pragma unroll
            for (int mt = 0; mt < 2; mt++)
#pragma unroll
                for (int nt = 0; nt < 8; nt++)
                    mma_f16(acc[mt][nt], af[mt][0], af[mt][1], af[mt][2], af[mt][3],
                            bf[nt >> 1][(nt & 1) * 2], bf[nt >> 1][(nt & 1) * 2 + 1]);
        }
    }

#pragma unroll
    for (int mt = 0; mt < 2; mt++) {
#pragma unroll
        for (int nt = 0; nt < 8; nt++) {
            int row = m0 + wm * 32 + mt * 16 + qr;
            int col = n0 + wn * 64 + nt * 8 + qc * 2;
            float bv0 = bias[col], bv1 = bias[col + 1];
            float v00 = acc[mt][nt][0] + bv0, v01 = acc[mt][nt][1] + bv1;
            float v10 = acc[mt][nt][2] + bv0, v11 = acc[mt][nt][3] + bv1;
            if (mode == 1) {
                *(float2*)(Cout + (size_t)row * NXD + col) = make_float2(v00, v01);
                *(float2*)(Cout + (size_t)(row + 8) * NXD + col) = make_float2(v10, v11);
            } else {
                int sec = col >> 10;
                int hn = col & 1023;
                int h = hn >> 6, d = hn & 63;
                int b0_ = row >> 10, s0_ = row & 1023;
                size_t i0 = (((size_t)b0_ * NHEAD + h) * SEQ + s0_) * HDIM + d;
                int b1_ = (row + 8) >> 10, s1_ = (row + 8) & 1023;
                size_t i1 = (((size_t)b1_ * NHEAD + h) * SEQ + s1_) * HDIM + d;
                if (sec == 0) {
                    *(uint32_t*)(g_q + i0) = packh2(v00 * QSCALE, v01 * QSCALE);
                    *(uint32_t*)(g_q + i1) = packh2(v10 * QSCALE, v11 * QSCALE);
                } else if (sec == 1) {
                    *(float2*)(present + i0) = make_float2(v00, v01);
                    *(float2*)(present + i1) = make_float2(v10, v11);
                    *(uint32_t*)(g_k + i0) = packh2(v00, v01);
                    *(uint32_t*)(g_k + i1) = packh2(v10, v11);
                } else {
                    float* pv = present + (size_t)BATCH * NHEAD * SEQ * HDIM;
                    *(float2*)(pv + i0) = make_float2(v00, v01);
                    *(float2*)(pv + i1) = make_float2(v10, v11);
                    *(uint32_t*)(g_v + i0) = packh2(v00, v01);
                    *(uint32_t*)(g_v + i1) = packh2(v10, v11);
                }
            }
        }
    }
}

// ---------------------------------------------------------------------------
// Attention role (R14-verified)
// ---------------------------------------------------------------------------
__device__ void run_attn(int xr, int h, int b, uint32_t* sm32)
{
    uint32_t* Qs = sm32;
    uint32_t* Ksb = Qs + 128 * TLD2;
    uint32_t* Vsb = Ksb + 2 * 64 * TLD2;

    const int t = threadIdx.x;
    const int lane = t & 31, w = t >> 5;
    const int qr = lane >> 2, qc = lane & 3;
    const int q0 = xr * 128;

    const __half* qptr = g_q + ((size_t)b * NHEAD + h) * SEQ * HDIM;
    const __half* kptr = g_k + ((size_t)b * NHEAD + h) * SEQ * HDIM;
    const __half* vptr = g_v + ((size_t)b * NHEAD + h) * SEQ * HDIM;

    const uint32_t qs_a = smem_u32(Qs);
    const uint32_t ks_a[2] = { smem_u32(Ksb), smem_u32(Ksb + 64 * TLD2) };
    const uint32_t vs_a[2] = { smem_u32(Vsb), smem_u32(Vsb + 64 * TLD2) };

    const int wrow = w * 16;
    const uint32_t qa_loff = ((wrow + (lane & 15)) * TLD2 + ((lane >> 4) << 2)) * 4;
    const uint32_t kb_loff = ((((lane >> 4) << 3) + (lane & 7)) * TLD2
                              + (((lane >> 3) & 1) << 2)) * 4;
    const uint32_t vt_loff = (((((lane >> 3) & 1) << 3) + (lane & 7)) * TLD2
                              + ((lane >> 4) << 2)) * 4;

#pragma unroll
    for (int i = 0; i < 4; i++) {
        int c = t + i * 256;
        int row = c >> 3, ch = c & 7;
        cp16(qs_a + ((uint32_t)row * TLD2 + ch * 4) * 4,
             qptr + (size_t)(q0 + row) * HDIM + ch * 8);
    }
#pragma unroll
    for (int i = 0; i < 2; i++) {
        int c = t + i * 256;
        int row = c >> 3, ch = c & 7;
        uint32_t off = ((uint32_t)row * TLD2 + ch * 4) * 4;
        cp16(ks_a[0] + off, kptr + (size_t)row * HDIM + ch * 8);
        cp16(vs_a[0] + off, vptr + (size_t)row * HDIM + ch * 8);
    }
    cp_commit();

    float oacc[8][4];
#pragma unroll
    for (int nt = 0; nt < 8; nt++)
#pragma unroll
        for (int r = 0; r < 4; r++) oacc[nt][r] = 0.f;
    float m0 = -1e30f, m1 = -1e30f, l0 = 0.f, l1 = 0.f;

    const int qg0 = q0 + wrow + qr;
    const int qg1 = qg0 + 8;
    const int qmax = q0 + wrow + 15;
    const int nj = xr * 2 + 2;

    asm volatile("cp.async.wait_group 0;" ::: "memory");
    __syncthreads();
    uint32_t qf[4][4];
#pragma unroll
    for (int ks = 0; ks < 4; ks++)
        ldsm4(qf[ks], qs_a + qa_loff + ks * 32);

    for (int jt = 0; jt < nj; jt++) {
        const int j0 = jt * 64;
        if (jt > 0) {
            asm volatile("cp.async.wait_group 0;" ::: "memory");
            __syncthreads();
        }
        if (jt + 1 < nj) {
            const int buf = (jt + 1) & 1;
            const int jr = (jt + 1) * 64;
#pragma unroll
            for (int i = 0; i < 2; i++) {
                int c = t + i * 256;
                int row = c >> 3, ch = c & 7;
                uint32_t off = ((uint32_t)row * TLD2 + ch * 4) * 4;
                cp16(ks_a[buf] + off, kptr + (size_t)(jr + row) * HDIM + ch * 8);
                cp16(vs_a[buf] + off, vptr + (size_t)(jr + row) * HDIM + ch * 8);
            }
            cp_commit();
        }
        if (j0 > qmax) continue;

        const uint32_t k_addr = ks_a[jt & 1] + kb_loff;
        const uint32_t v_addr = vs_a[jt & 1] + vt_loff;

        float sacc[8][4];
#pragma unroll
        for (int nt = 0; nt < 8; nt++)
#pragma unroll
            for (int r = 0; r < 4; r++) sacc[nt][r] = 0.f;

#pragma unroll
        for (int ks = 0; ks < 4; ks++) {
            uint32_t kf[4][4];
#pragma unroll
            for (int p = 0; p < 4; p++)
                ldsm4(kf[p], k_addr + p * 16 * TLD2 * 4 + ks * 32);
#pragma unroll
            for (int nt = 0; nt < 8; nt++)
                mma_f16(sacc[nt], qf[ks][0], qf[ks][1], qf[ks][2], qf[ks][3],
                        kf[nt >> 1][(nt & 1) * 2], kf[nt >> 1][(nt & 1) * 2 + 1]);
        }

        float rx0 = -1e30f, rx1 = -1e30f;
        if (j0 + 63 > q0 + wrow) {
#pragma unroll
            for (int nt = 0; nt < 8; nt++) {
                int kg = j0 + nt * 8 + qc * 2;
                if (kg > qg0)     sacc[nt][0] = -1e30f;
                if (kg + 1 > qg0) sacc[nt][1] = -1e30f;
                if (kg > qg1)     sacc[nt][2] = -1e30f;
                if (kg + 1 > qg1) sacc[nt][3] = -1e30f;
            }
        }
#pragma unroll
        for (int nt = 0; nt < 8; nt++) {
            rx0 = fmaxf(rx0, fmaxf(sacc[nt][0], sacc[nt][1]));
            rx1 = fmaxf(rx1, fmaxf(sacc[nt][2], sacc[nt][3]));
        }
        rx0 = fmaxf(rx0, __shfl_xor_sync(0xffffffffu, rx0, 1));
        rx0 = fmaxf(rx0, __shfl_xor_sync(0xffffffffu, rx0, 2));
        rx1 = fmaxf(rx1, __shfl_xor_sync(0xffffffffu, rx1, 1));
        rx1 = fmaxf(rx1, __shfl_xor_sync(0xffffffffu, rx1, 2));

        float nm0 = fmaxf(m0, rx0), nm1 = fmaxf(m1, rx1);
        float cr0 = exp2f(m0 - nm0), cr1 = exp2f(m1 - nm1);

        float rs0 = 0.f, rs1 = 0.f;
        uint32_t plo[8], phi[8];
#pragma unroll
        for (int nt = 0; nt < 8; nt++) {
            float p00 = exp2f(sacc[nt][0] - nm0);
            float p01 = exp2f(sacc[nt][1] - nm0);
            float p10 = exp2f(sacc[nt][2] - nm1);
            float p11 = exp2f(sacc[nt][3] - nm1);
            rs0 += p00 + p01;
            rs1 += p10 + p11;
            plo[nt] = packh2(p00, p01);
            phi[nt] = packh2(p10, p11);
        }
        rs0 += __shfl_xor_sync(0xffffffffu, rs0, 1);
        rs0 += __shfl_xor_sync(0xffffffffu, rs0, 2);
        rs1 += __shfl_xor_sync(0xffffffffu, rs1, 1);
        rs1 += __shfl_xor_sync(0xffffffffu, rs1, 2);

        l0 = l0 * cr0 + rs0;  m0 = nm0;
        l1 = l1 * cr1 + rs1;  m1 = nm1;
#pragma unroll
        for (int nt = 0; nt < 8; nt++) {
            oacc[nt][0] *= cr0;  oacc[nt][1] *= cr0;
            oacc[nt][2] *= cr1;  oacc[nt][3] *= cr1;
        }

#pragma unroll
        for (int j = 0; j < 4; j++) {
            uint32_t vf[4][4];
#pragma unroll
            for (int p = 0; p < 4; p++)
                ldsm4t(vf[p], v_addr + j * 16 * TLD2 * 4 + p * 32);
            uint32_t a0 = plo[2 * j], a1 = phi[2 * j];
            uint32_t a2 = plo[2 * j + 1], a3 = phi[2 * j + 1];
#pragma unroll
            for (int nt = 0; nt < 8; nt++)
                mma_f16(oacc[nt], a0, a1, a2, a3,
                        vf[nt >> 1][(nt & 1) * 2], vf[nt >> 1][(nt & 1) * 2 + 1]);
        }
    }

    __syncthreads();
    float inv0 = 1.f / l0, inv1 = 1.f / l1;
#pragma unroll
    for (int nt = 0; nt < 8; nt++) {
        Qs[(wrow + qr) * TLD2 + nt * 4 + qc] =
            packh2(oacc[nt][0] * inv0, oacc[nt][1] * inv0);
        Qs[(wrow + qr + 8) * TLD2 + nt * 4 + qc] =
            packh2(oacc[nt][2] * inv1, oacc[nt][3] * inv1);
    }
    __syncthreads();
    for (int idx = t; idx < 128 * 32; idx += 256) {
        int row = idx >> 5, c2 = idx & 31;
        *(uint32_t*)(g_a + ((size_t)b * SEQ + q0 + row) * NXD + h * HDIM + c2 * 2) =
            Qs[row * TLD2 + c2];
    }
}

// ---------------------------------------------------------------------------
// Fused persistent kernel: 296 workers pull from the global queue.
// [0,768): qkv; [768,1280): attn (long-first); [1280,1536): proj
// (proj ordered sblock-DESC to match attn completion order).
// ---------------------------------------------------------------------------
__global__ void __launch_bounds__(256, 2) fused_kernel(
    const float* __restrict__ b_attn, const float* __restrict__ b_proj,
    float* __restrict__ out, float* __restrict__ present)
{
    extern __shared__ uint32_t sm32[];
    __shared__ int s_item;

    for (;;) {
        if (threadIdx.x == 0) s_item = atomicAdd(&g_cursor, 1);
        __syncthreads();
        const int i = s_item;
        if (i >= N_ITEMS) return;

        if (i < N_QKV) {
            const int m = i / 24, n = i % 24;
            run_gemm(g_x, g_wT_attn, b_attn, nullptr, present, 0,
                     m * 128, n * 128, sm32);
            __syncthreads();
            if (threadIdx.x == 0) {
                __threadfence();
                atomicAdd(&g_qkv_done[m], 1);
            }
        } else if (i < N_QKV + N_ATTN) {
            const int j = i - N_QKV;
            const int xr = 7 - (j >> 6);         // long tiles first
            const int h = (j & 63) >> 2;
            const int b = j & 3;
            if (threadIdx.x == 0) {
                for (int s = 0; s <= xr; s++)
                    spin_until(&g_qkv_done[b * 8 + s], 24);
            }
            __syncthreads();
            __threadfence();
            run_attn(xr, h, b, sm32);
            __syncthreads();
            if (threadIdx.x == 0) {
                __threadfence();
                atomicAdd(&g_attn_done[b * 8 + xr], 1);
            }
        } else {
            const int p = i - N_QKV - N_ATTN;
            const int mi = p >> 3;
            const int bq = mi >> 3;
            const int sb = 7 - (mi & 7);         // match attn long-first completion
            const int m = bq * 8 + sb;
            const int n = p & 7;
            if (threadIdx.x == 0)
                spin_until(&g_attn_done[m], 16);
            __syncthreads();
            __threadfence();
            run_gemm(g_a, g_wT_proj, b_proj, out, nullptr, 1,
                     m * 128, n * 128, sm32);
        }
        __syncthreads();
    }
}

// ---------------------------------------------------------------------------
extern "C" void kernel_launch(void* const* d_in, const int* in_sizes, int n_in,
                              void* d_out, int out_size)
{
    const float* x      = (const float*)d_in[0];
    const float* w_attn = (const float*)d_in[1];
    const float* b_attn = (const float*)d_in[2];
    const float* w_proj = (const float*)d_in[3];
    const float* b_proj = (const float*)d_in[4];

    float* out = (float*)d_out;
    float* present = out + (size_t)BATCH * SEQ * NXD;  // (2,B,NH,S,HD)

    cudaFuncSetAttribute(fused_kernel,
                         cudaFuncAttributeMaxDynamicSharedMemorySize, FUSED_SMEM);

    prep_kernel<<<8192, 256>>>(x, w_attn, w_proj);
    fused_kernel<<<296, 256, FUSED_SMEM>>>(b_attn, b_proj, out, present);
}